// round 2
// baseline (speedup 1.0000x reference)
#include <cuda_runtime.h>
#include <cstdint>

#define BSZ  32
#define SEQL 64
#define HID  256

// scratch (no cudaMalloc allowed)
__device__ float g_context[BSZ * HID];

// ---------- helpers ----------
__device__ __forceinline__ uint32_t s2u(const void* p) {
    uint32_t a;
    asm("{ .reg .u64 t; cvta.to.shared.u64 t, %1; cvt.u32.u64 %0, t; }" : "=r"(a) : "l"(p));
    return a;
}
__device__ __forceinline__ void ffma2(unsigned long long& d, unsigned long long a, unsigned long long b) {
    asm("fma.rn.f32x2 %0, %1, %2, %3;" : "=l"(d) : "l"(a), "l"(b), "l"(d));
}
__device__ __forceinline__ unsigned long long pk2(float a, float b) {
    unsigned long long r;
    asm("mov.b64 %0, {%1, %2};" : "=l"(r) : "f"(a), "f"(b));
    return r;
}
__device__ __forceinline__ float2 upk2(unsigned long long v) {
    float2 f;
    asm("mov.b64 {%0, %1}, %2;" : "=f"(f.x), "=f"(f.y) : "l"(v));
    return f;
}
__device__ __forceinline__ float sigf(float x)      { return 1.0f / (1.0f + __expf(-x)); }
__device__ __forceinline__ float tanh_fast(float x) { return 1.0f - 2.0f / (__expf(2.0f * x) + 1.0f); }

// ============================================================================
// K1: context[b][h] = sum_s softmax_s(x[b]@Wa_x)[s,h] * x[b,s,h]
// grid 128 = (b:32) x (hchunk:4), 256 threads
// ============================================================================
__global__ void __launch_bounds__(256) k_context(const float* __restrict__ x,
                                                 const float* __restrict__ Wa) {
    __shared__ __align__(16) float xt[64][65];     // x chunk transposed [k][s] (padded)
    __shared__ __align__(16) float wt_sc[64][64];  // Wa tile during GEMM, scores afterwards

    const int b   = blockIdx.x >> 2;
    const int hc  = blockIdx.x & 3;
    const int tid = threadIdx.x;
    const int h4  = tid & 15;   // h-group (4 cols each)
    const int s4  = tid >> 4;   // s-group (4 rows each)
    const float* xb = x + b * SEQL * HID;

    float acc[4][4];
#pragma unroll
    for (int i = 0; i < 4; i++)
#pragma unroll
        for (int j = 0; j < 4; j++) acc[i][j] = 0.0f;

    for (int kt = 0; kt < 4; ++kt) {
        // load x chunk transposed: xt[kk][s] = x[b][s][kt*64+kk]
#pragma unroll
        for (int it = 0; it < 16; ++it) {
            int i = it * 256 + tid;
            int s = i >> 6, kk = i & 63;
            xt[kk][s] = xb[s * HID + kt * 64 + kk];
        }
        // load Wa tile: wt[kk][hl] = Wa[(kt*64+kk)*H + hc*64+hl]
#pragma unroll
        for (int it = 0; it < 16; ++it) {
            int i = it * 256 + tid;
            int kk = i >> 6, hl = i & 63;
            wt_sc[kk][hl] = Wa[(kt * 64 + kk) * HID + hc * 64 + hl];
        }
        __syncthreads();
#pragma unroll 4
        for (int kk = 0; kk < 64; ++kk) {
            float a0 = xt[kk][s4 * 4 + 0];
            float a1 = xt[kk][s4 * 4 + 1];
            float a2 = xt[kk][s4 * 4 + 2];
            float a3 = xt[kk][s4 * 4 + 3];
            float4 wv = *reinterpret_cast<const float4*>(&wt_sc[kk][h4 * 4]);
            acc[0][0] += a0 * wv.x; acc[0][1] += a0 * wv.y; acc[0][2] += a0 * wv.z; acc[0][3] += a0 * wv.w;
            acc[1][0] += a1 * wv.x; acc[1][1] += a1 * wv.y; acc[1][2] += a1 * wv.z; acc[1][3] += a1 * wv.w;
            acc[2][0] += a2 * wv.x; acc[2][1] += a2 * wv.y; acc[2][2] += a2 * wv.z; acc[2][3] += a2 * wv.w;
            acc[3][0] += a3 * wv.x; acc[3][1] += a3 * wv.y; acc[3][2] += a3 * wv.z; acc[3][3] += a3 * wv.w;
        }
        __syncthreads();
    }

    // write scores into wt_sc reused as sc[s][hl]
#pragma unroll
    for (int i = 0; i < 4; ++i) {
        *reinterpret_cast<float4*>(&wt_sc[s4 * 4 + i][h4 * 4]) =
            make_float4(acc[i][0], acc[i][1], acc[i][2], acc[i][3]);
    }
    __syncthreads();

    // softmax over s + weighted sum with x
    if (tid < 64) {
        const int h = tid;
        float m = -3.4e38f;
#pragma unroll 8
        for (int s = 0; s < 64; ++s) m = fmaxf(m, wt_sc[s][h]);
        float Z = 0.0f, C = 0.0f;
#pragma unroll 8
        for (int s = 0; s < 64; ++s) {
            float e = __expf(wt_sc[s][h] - m);
            Z += e;
            C += e * xb[s * HID + hc * 64 + h];
        }
        g_context[b * HID + hc * 64 + h] = C / Z;
    }
}

// ============================================================================
// K3: LSTM recurrence. 16 clusters of 8 CTAs, 2 batches/cluster,
// each CTA owns h in [rank*32, rank*32+32) -> 128 gate cols, Wh slice in regs.
// ============================================================================
__global__ void __cluster_dims__(8, 1, 1) __launch_bounds__(512, 1)
k_recur(const float* __restrict__ Wi, const float* __restrict__ Wh,
        const float* __restrict__ bias, const float* __restrict__ Wf,
        const float* __restrict__ bf, float* __restrict__ out) {
    __shared__ __align__(16) float htbuf[2][2][256];       // double-buffered full ht
    __shared__ __align__(16) float ctx_s[2][256];
    __shared__ float gbase_s[2][128];
    __shared__ float gates_s[2][128];
    __shared__ float partial_s[2][128][9];                 // padded pitch 9
    __shared__ float ct_s[2][32];
    __shared__ float hstage[2][32];
    __shared__ float red_s[16];

    const int tid = threadIdx.x;
    uint32_t rnk;
    asm("mov.u32 %0, %%cluster_ctarank;" : "=r"(rnk));
    const int r     = (int)rnk;
    const int cidx  = blockIdx.x >> 3;
    const int cbase = cidx * 2;          // first batch index of this cluster
    const int kq    = tid >> 6;          // k-chunk 0..7 (32 k's each)
    const int cp    = tid & 63;          // column pair 0..63
    const int cl0   = 2 * cp, cl1 = 2 * cp + 1;
    const int col0  = (cl0 >> 5) * 256 + r * 32 + (cl0 & 31);
    const int col1  = (cl1 >> 5) * 256 + r * 32 + (cl1 & 31);

    // ---- init smem ----
    for (int i = tid; i < 2 * 2 * 256; i += 512) ((float*)htbuf)[i] = 0.0f;
    if (tid < 64) { ((float*)ct_s)[tid] = 0.0f; ((float*)hstage)[tid] = 0.0f; }
    {
        int b2 = tid >> 8, k = tid & 255;   // exactly 512 values
        ctx_s[b2][k] = g_context[(cbase + b2) * HID + k];
    }
    __syncthreads();

    // ---- gbase = bias + context @ Wi (512 threads: cl x 4 k-chunks) ----
    {
        int cl = tid & 127, kh = tid >> 7;
        int col = (cl >> 5) * 256 + r * 32 + (cl & 31);
        float a0 = 0.0f, a1 = 0.0f;
#pragma unroll 8
        for (int k = kh * 64; k < kh * 64 + 64; ++k) {
            float w = Wi[k * 1024 + col];
            a0 += ctx_s[0][k] * w;
            a1 += ctx_s[1][k] * w;
        }
        partial_s[0][cl][kh] = a0;
        partial_s[1][cl][kh] = a1;
    }
    __syncthreads();
    if (tid < 256) {
        int b2 = tid >> 7, cl = tid & 127;
        int col = (cl >> 5) * 256 + r * 32 + (cl & 31);
        gbase_s[b2][cl] = bias[col] + partial_s[b2][cl][0] + partial_s[b2][cl][1]
                        + partial_s[b2][cl][2] + partial_s[b2][cl][3];
    }

    // ---- load Wh slice into registers (packed k-pairs for f32x2 FMA) ----
    unsigned long long wp0[16], wp1[16];
#pragma unroll
    for (int p = 0; p < 16; ++p) {
        int k = kq * 32 + 2 * p;
        wp0[p] = pk2(Wh[k * 1024 + col0], Wh[(k + 1) * 1024 + col0]);
        wp1[p] = pk2(Wh[k * 1024 + col1], Wh[(k + 1) * 1024 + col1]);
    }
    __syncthreads();
    asm volatile("barrier.cluster.arrive.aligned;" ::: "memory");
    asm volatile("barrier.cluster.wait.aligned;" ::: "memory");

    const uint32_t ht_base_u = s2u(&htbuf[0][0][0]);

    // ---- 64 recurrence steps ----
    for (int t = 0; t < 64; ++t) {
        const int p = t & 1;
        const uint32_t hb = ht_base_u + (uint32_t)(p * 2048 + kq * 128);
#pragma unroll
        for (int b2 = 0; b2 < 2; ++b2) {
            unsigned long long acc0 = 0ull, acc1 = 0ull;
            const uint32_t a = hb + (uint32_t)(b2 * 1024);
#pragma unroll
            for (int q = 0; q < 8; ++q) {
                unsigned long long hA, hB;
                asm volatile("ld.shared.v2.u64 {%0, %1}, [%2];"
                             : "=l"(hA), "=l"(hB) : "r"(a + (uint32_t)(q * 16)));
                ffma2(acc0, wp0[2 * q],     hA);
                ffma2(acc0, wp0[2 * q + 1], hB);
                ffma2(acc1, wp1[2 * q],     hA);
                ffma2(acc1, wp1[2 * q + 1], hB);
            }
            float2 f0 = upk2(acc0), f1 = upk2(acc1);
            partial_s[b2][cl0][kq] = f0.x + f0.y;
            partial_s[b2][cl1][kq] = f1.x + f1.y;
        }
        __syncthreads();

        if (tid < 256) {
            int b2 = tid >> 7, cl = tid & 127;
            float g = gbase_s[b2][cl];
#pragma unroll
            for (int k8 = 0; k8 < 8; ++k8) g += partial_s[b2][cl][k8];
            gates_s[b2][cl] = g;
        }
        __syncthreads();

        if (tid < 64) {
            int b2 = tid >> 5, hl = tid & 31;
            float gi = gates_s[b2][hl];
            float gf = gates_s[b2][32 + hl];
            float gg = gates_s[b2][64 + hl];
            float go = gates_s[b2][96 + hl];
            float c  = sigf(gf) * ct_s[b2][hl] + sigf(gi) * tanh_fast(gg);
            ct_s[b2][hl]   = c;
            hstage[b2][hl] = sigf(go) * tanh_fast(c);
        }
        __syncthreads();

        // scatter ht_new slice into every cluster CTA's htbuf[p^1]
        {
            int rr = tid >> 6;           // target rank
            int e  = tid & 63;
            int b2 = e >> 5, hl = e & 31;
            float v = hstage[b2][hl];
            uint32_t laddr = ht_base_u + (uint32_t)(((p ^ 1) * 512 + b2 * 256 + r * 32 + hl) * 4);
            uint32_t raddr;
            asm("mapa.shared::cluster.u32 %0, %1, %2;" : "=r"(raddr) : "r"(laddr), "r"(rr));
            asm volatile("st.shared::cluster.f32 [%0], %1;" :: "r"(raddr), "f"(v));
        }
        asm volatile("barrier.cluster.arrive.aligned;" ::: "memory");
        asm volatile("barrier.cluster.wait.aligned;" ::: "memory");
    }

    // ---- epilogue: out[b] = ht @ Wf + bf (rank 0 of each cluster) ----
    if (r == 0) {
        int b2 = tid >> 8, k = tid & 255;
        float v = htbuf[0][b2][k] * Wf[k];
#pragma unroll
        for (int off = 16; off > 0; off >>= 1) v += __shfl_xor_sync(0xffffffffu, v, off);
        if ((tid & 31) == 0) red_s[tid >> 5] = v;
        __syncthreads();
        if (tid == 0) {
            float o = bf[0];
#pragma unroll
            for (int w = 0; w < 8; ++w) o += red_s[w];
            out[cbase] = o;
        }
        if (tid == 256) {
            float o = bf[0];
#pragma unroll
            for (int w = 8; w < 16; ++w) o += red_s[w];
            out[cbase + 1] = o;
        }
    }
}

// ============================================================================
extern "C" void kernel_launch(void* const* d_in, const int* in_sizes, int n_in,
                              void* d_out, int out_size) {
    (void)in_sizes; (void)n_in; (void)out_size;
    const float* x    = (const float*)d_in[0];
    const float* Wa   = (const float*)d_in[1];
    // d_in[2] = ba : cancels inside softmax, unused
    const float* Wi   = (const float*)d_in[3];
    const float* Wh   = (const float*)d_in[4];
    const float* bias = (const float*)d_in[5];
    const float* Wf   = (const float*)d_in[6];
    const float* bf   = (const float*)d_in[7];
    float* out = (float*)d_out;

    k_context<<<128, 256>>>(x, Wa);
    k_recur<<<128, 512>>>(Wi, Wh, bias, Wf, bf, out);
}